// round 15
// baseline (speedup 1.0000x reference)
#include <cuda_runtime.h>
#include <cuda_fp16.h>
#include <math.h>

#define NN 50000
#define NE 500000
#define BATCH 10000

// ---------------- scratch ----------------
__device__ __half g_xh[NN * 128];       // fp16 node features (GEMM input)
__device__ __half g_qh[NN * 128];       // fp16 q
__device__ __half g_kvh[NN * 256];      // fp16 kv channel-interleaved (k_c,v_c)
__device__ __half g_skiph[NN * 128];    // fp16 skip
__device__ float  g_accs[NN * 132];     // [acc NN*128 | s NN*4] one memset
__device__ __half g_h2[NN * 128];
__device__ __half g_Wch[2][512 * 128];  // concat weights, n-major fp16 (both layers)
__device__ float  g_bc[2][512];
__device__ __half g_Weh[2][128 * 64];   // edge weights, n-major fp16 (both layers)
__device__ int    g_eidx[NE];
__device__ int    g_cnt;

__device__ __forceinline__ unsigned h2u(__half2 h) {
    unsigned u;
    *reinterpret_cast<__half2*>(&u) = h;
    return u;
}

__device__ __forceinline__ void cp16(void* smem, const void* gmem, bool pred) {
    unsigned sa = (unsigned)__cvta_generic_to_shared(smem);
    int sz = pred ? 16 : 0;
    asm volatile("cp.async.cg.shared.global [%0], [%1], 16, %2;"
                 :: "r"(sa), "l"(gmem), "r"(sz) : "memory");
}

// ============ PROLOGUE mega-kernel: compact | gather | concat_w | prep_we ===
#define PB_CONCAT 128
#define PB_PREP   64
#define PB_GATHER 3125
#define PB_COMPACT 1954

__global__ __launch_bounds__(256) void prologue(
    const int* __restrict__ n_id, const float* __restrict__ emb,
    const int* __restrict__ ei,
    const float* __restrict__ qW1, const float* __restrict__ kW1,
    const float* __restrict__ vW1, const float* __restrict__ sW1,
    const float* __restrict__ qb1, const float* __restrict__ kb1,
    const float* __restrict__ vb1, const float* __restrict__ sb1,
    const float* __restrict__ qW2, const float* __restrict__ kW2,
    const float* __restrict__ vW2, const float* __restrict__ sW2,
    const float* __restrict__ qb2, const float* __restrict__ kb2,
    const float* __restrict__ vb2, const float* __restrict__ sb2,
    const float* __restrict__ We1, const float* __restrict__ We2) {
    __shared__ float tile[32][33];
    const int bx = blockIdx.x;
    const int tid = threadIdx.x;

    if (bx < PB_CONCAT) {
        const float* Ws[8] = {qW1, kW1, vW1, sW1, qW2, kW2, vW2, sW2};
        const float* bs[8] = {qb1, kb1, vb1, sb1, qb2, kb2, vb2, sb2};
        int id = bx >> 4;
        int ky = (bx >> 2) & 3, cz = bx & 3;
        int layer = id >> 2, which = id & 3;
        int k0 = ky * 32, c0 = cz * 32;
        const float* W = Ws[id];
        int tx = tid & 31, ty = tid >> 5;
#pragma unroll
        for (int i = 0; i < 4; i++)
            tile[ty + i * 8][tx] = W[(k0 + ty + i * 8) * 128 + c0 + tx];
        __syncthreads();
#pragma unroll
        for (int i = 0; i < 4; i++) {
            int c = c0 + ty + i * 8;
            g_Wch[layer][(which * 128 + c) * 128 + k0 + tx] =
                __float2half(tile[tx][ty + i * 8]);
        }
        if (ky == 0 && ty == 0)
            g_bc[layer][which * 128 + c0 + tx] = bs[id][c0 + tx];
    } else if (bx < PB_CONCAT + PB_PREP) {
        int i = (bx - PB_CONCAT) * 256 + tid;
        int layer = i >= 64 * 128;
        int j = i - layer * 64 * 128;
        int k = j >> 7, n = j & 127;
        const float* We = layer ? We2 : We1;
        g_Weh[layer][n * 64 + k] = __float2half(We[j]);
    } else if (bx < PB_CONCAT + PB_PREP + PB_GATHER) {
        int idx = (bx - PB_CONCAT - PB_PREP) * 256 + tid;
        int i = idx >> 4;
        int c = (idx & 15) * 8;
        const float4* src = (const float4*)&emb[(size_t)n_id[i] * 128 + c];
        float4 v0 = src[0], v1 = src[1];
        uint4 o;
        o.x = h2u(__floats2half2_rn(v0.x, v0.y));
        o.y = h2u(__floats2half2_rn(v0.z, v0.w));
        o.z = h2u(__floats2half2_rn(v1.x, v1.y));
        o.w = h2u(__floats2half2_rn(v1.z, v1.w));
        *(uint4*)&g_xh[i * 128 + c] = o;
    } else {
        int e = (bx - PB_CONCAT - PB_PREP - PB_GATHER) * 256 + tid;
        if (e < NE && ei[NE + e] < BATCH) {
            int slot = atomicAdd(&g_cnt, 1);
            g_eidx[slot] = e;
        }
    }
}

// ---------------- shared GEMM tile body (fp16 m16n8k16, cp.async 2-stage) ---
// outputs: q -> Cq[row*128+col], k/v -> Ckv interleaved, s -> Cs
__device__ __forceinline__ void gemm_tile_body(
    const __half* __restrict__ A, const __half* __restrict__ W,
    const float* __restrict__ bias, __half* __restrict__ Cq,
    __half* __restrict__ Ckv, __half* __restrict__ Cs,
    int M, int m0, int n0) {
    __shared__ __half As[2][128][40];
    __shared__ __half Bs[2][128][40];
    const int tid = threadIdx.x;
    const int lane = tid & 31, wid = tid >> 5;
    const int wm = (wid & 3) * 32, wn = (wid >> 2) * 64;
    const int g = lane >> 2, t = lane & 3;
    const int lrow = tid >> 1;
    const int lcol = (tid & 1) * 16;
    const int gr = m0 + lrow;
    const bool aval = gr < M;
    const __half* abase = &A[(size_t)(aval ? gr : 0) * 128 + lcol];
    const __half* bbase = &W[(size_t)(n0 + lrow) * 128 + lcol];

    float acc[2][8][4];
#pragma unroll
    for (int i = 0; i < 2; i++)
#pragma unroll
        for (int j = 0; j < 8; j++)
#pragma unroll
            for (int c = 0; c < 4; c++) acc[i][j][c] = 0.f;

#pragma unroll
    for (int it = 0; it < 2; it++) {
        int k0 = it * 32;
        cp16(&As[it][lrow][lcol],     abase + k0, aval);
        cp16(&As[it][lrow][lcol + 8], abase + k0 + 8, aval);
        cp16(&Bs[it][lrow][lcol],     bbase + k0, true);
        cp16(&Bs[it][lrow][lcol + 8], bbase + k0 + 8, true);
        asm volatile("cp.async.commit_group;" ::: "memory");
    }

#pragma unroll
    for (int it = 0; it < 4; it++) {
        if (it < 3)
            asm volatile("cp.async.wait_group 1;" ::: "memory");
        else
            asm volatile("cp.async.wait_group 0;" ::: "memory");
        __syncthreads();
        const int buf = it & 1;
#pragma unroll
        for (int kk = 0; kk < 32; kk += 16) {
            unsigned af[2][4];
#pragma unroll
            for (int i = 0; i < 2; i++) {
                int r = wm + i * 16 + g;
                af[i][0] = *(const unsigned*)&As[buf][r][kk + 2 * t];
                af[i][1] = *(const unsigned*)&As[buf][r + 8][kk + 2 * t];
                af[i][2] = *(const unsigned*)&As[buf][r][kk + 2 * t + 8];
                af[i][3] = *(const unsigned*)&As[buf][r + 8][kk + 2 * t + 8];
            }
            unsigned bf[8][2];
#pragma unroll
            for (int j = 0; j < 8; j++) {
                int n = wn + j * 8 + g;
                bf[j][0] = *(const unsigned*)&Bs[buf][n][kk + 2 * t];
                bf[j][1] = *(const unsigned*)&Bs[buf][n][kk + 2 * t + 8];
            }
#pragma unroll
            for (int i = 0; i < 2; i++)
#pragma unroll
                for (int j = 0; j < 8; j++) {
                    float* c = acc[i][j];
                    asm volatile(
                        "mma.sync.aligned.m16n8k16.row.col.f32.f16.f16.f32 "
                        "{%0,%1,%2,%3}, {%4,%5,%6,%7}, {%8,%9}, {%0,%1,%2,%3};"
                        : "+f"(c[0]), "+f"(c[1]), "+f"(c[2]), "+f"(c[3])
                        : "r"(af[i][0]), "r"(af[i][1]), "r"(af[i][2]),
                          "r"(af[i][3]), "r"(bf[j][0]), "r"(bf[j][1]));
                }
        }
        __syncthreads();
        if (it + 2 < 4) {
            int k0 = (it + 2) * 32;
            cp16(&As[buf][lrow][lcol],     abase + k0, aval);
            cp16(&As[buf][lrow][lcol + 8], abase + k0 + 8, aval);
            cp16(&Bs[buf][lrow][lcol],     bbase + k0, true);
            cp16(&Bs[buf][lrow][lcol + 8], bbase + k0 + 8, true);
            asm volatile("cp.async.commit_group;" ::: "memory");
        }
    }
#pragma unroll
    for (int i = 0; i < 2; i++) {
        int r0 = m0 + wm + i * 16 + g;
#pragma unroll
        for (int j = 0; j < 8; j++) {
            int col = n0 + wn + j * 8 + t * 2;
            float b0 = bias[col], b1 = bias[col + 1];
#pragma unroll
            for (int rr = 0; rr < 2; rr++) {
                int row = r0 + rr * 8;
                if (row < M) {
                    float o0 = acc[i][j][rr * 2 + 0] + b0;
                    float o1 = acc[i][j][rr * 2 + 1] + b1;
                    if (col < 128) {
                        *(__half2*)&Cq[(size_t)row * 128 + col] =
                            __floats2half2_rn(o0, o1);
                    } else if (col < 384) {
                        int is_v = col >= 256;
                        int c = col & 127;
                        __half* kvp = &Ckv[(size_t)row * 256 + 2 * c + is_v];
                        kvp[0] = __float2half(o0);
                        kvp[2] = __float2half(o1);
                    } else {
                        *(__half2*)&Cs[(size_t)row * 128 + col - 384] =
                            __floats2half2_rn(o0, o1);
                    }
                }
            }
        }
    }
}

// layer-1 node GEMM: grid (391, 4)
__global__ __launch_bounds__(256) void node_gemm_h(
    const __half* __restrict__ A, const __half* __restrict__ W,
    const float* __restrict__ bias, __half* __restrict__ Cq,
    __half* __restrict__ Ckv, __half* __restrict__ Cs) {
    gemm_tile_body(A, W, bias, Cq, Ckv, Cs, NN, blockIdx.x * 128,
                   blockIdx.y * 128);
}

// layer-2 node GEMM, single launch: q(BATCH) | k,v(NN) | s(BATCH)
__global__ __launch_bounds__(256) void node_gemm_l2(
    const __half* __restrict__ A, const __half* __restrict__ W,
    const float* __restrict__ bias, __half* __restrict__ Cq,
    __half* __restrict__ Ckv, __half* __restrict__ Cs) {
    const int GB_B = (BATCH + 127) / 128;   // 79
    const int GB_N = (NN + 127) / 128;      // 391
    int bx = blockIdx.x;
    int m0, n0, M;
    if (bx < GB_B) {
        m0 = bx * 128; n0 = 0; M = BATCH;
    } else if (bx < GB_B + 2 * GB_N) {
        int idx = bx - GB_B;
        m0 = (idx % GB_N) * 128; n0 = 128 + (idx / GB_N) * 128; M = NN;
    } else {
        m0 = (bx - GB_B - 2 * GB_N) * 128; n0 = 384; M = BATCH;
    }
    gemm_tile_body(A, W, bias, Cq, Ckv, Cs, M, m0, n0);
}

// ===== FUSED edge kernel: attr build + E GEMM (smem) + alpha/agg atomics =====
__global__ __launch_bounds__(256) void edge_fused(
    const float* __restrict__ feats, const float* __restrict__ times,
    const float* __restrict__ tw, const float* __restrict__ tb,
    const __half* __restrict__ Weh,
    const int* __restrict__ eidx, const int* __restrict__ cntp, int cnt_c,
    const int* __restrict__ ei, const __half* __restrict__ qh,
    const __half* __restrict__ kvh,
    float* __restrict__ s, float* __restrict__ acc) {
    const int cnt = cntp ? *cntp : cnt_c;
    const int m0 = blockIdx.x * 128;
    if (m0 >= cnt) return;

    __shared__ __align__(16) char sbuf[36864];
    __half (*As)[72] = (__half(*)[72])sbuf;                 // [128][72]
    __half (*Bs)[72] = (__half(*)[72])(sbuf + 18432);       // [128][72]
    __half (*Es)[136] = (__half(*)[136])sbuf;               // overlaps (phase 2+)

    const int tid = threadIdx.x;
    const int lane = tid & 31, wid = tid >> 5;
    const int wm = (wid & 3) * 32, wn = (wid >> 2) * 64;
    const int g = lane >> 2, t = lane & 3;

    float accf[2][8][4];
#pragma unroll
    for (int i = 0; i < 2; i++)
#pragma unroll
        for (int j = 0; j < 8; j++)
#pragma unroll
            for (int c = 0; c < 4; c++) accf[i][j][c] = 0.f;

    // ---- phase 1: build A (edge attr) + B (We) tiles ----
    const int lrow = tid >> 1;
    const int hs = tid & 1;
    {
        int r = m0 + lrow;
        bool valid = r < cnt;
        int eid = valid ? (eidx ? eidx[r] : r) : 0;
        if (hs == 0) {   // feats cols 0..31
#pragma unroll
            for (int c = 0; c < 4; c++) {
                float4 v0, v1;
                if (valid) {
                    const float4* fp = (const float4*)&feats[(size_t)eid * 32 + c * 8];
                    v0 = fp[0]; v1 = fp[1];
                } else {
                    v0 = v1 = make_float4(0.f, 0.f, 0.f, 0.f);
                }
                uint4 o;
                o.x = h2u(__floats2half2_rn(v0.x, v0.y));
                o.y = h2u(__floats2half2_rn(v0.z, v0.w));
                o.z = h2u(__floats2half2_rn(v1.x, v1.y));
                o.w = h2u(__floats2half2_rn(v1.z, v1.w));
                *(uint4*)&As[lrow][c * 8] = o;
            }
        } else {         // time-embedding cols 32..63
            float tv = valid ? times[eid] : 0.f;
#pragma unroll
            for (int c = 0; c < 4; c++) {
                float cv[8];
#pragma unroll
                for (int u = 0; u < 8; u++) {
                    int j = c * 8 + u;
                    cv[u] = __cosf(tv * __ldg(&tw[j]) + __ldg(&tb[j]));
                }
                uint4 o;
                o.x = h2u(__floats2half2_rn(cv[0], cv[1]));
                o.y = h2u(__floats2half2_rn(cv[2], cv[3]));
                o.z = h2u(__floats2half2_rn(cv[4], cv[5]));
                o.w = h2u(__floats2half2_rn(cv[6], cv[7]));
                *(uint4*)&As[lrow][32 + c * 8] = o;
            }
        }
        const uint4* bp = (const uint4*)&Weh[lrow * 64 + hs * 32];
        uint4* bd = (uint4*)&Bs[lrow][hs * 32];
        bd[0] = bp[0]; bd[1] = bp[1]; bd[2] = bp[2]; bd[3] = bp[3];
    }

    // ---- prefetch src/dst for this warp's 16 edges (coalesced, pre-sync) ----
    const int base = wid * 16;
    int pf_sd;
    {
        int u = lane & 15;
        int r = m0 + base + u;
        int rr = r < cnt ? r : cnt - 1;
        int eid = eidx ? __ldg(&eidx[rr]) : rr;
        pf_sd = (lane < 16) ? __ldg(&ei[eid]) : __ldg(&ei[NE + eid]);
    }
    __syncthreads();

    // ---- MMA over K=64 ----
#pragma unroll
    for (int kk = 0; kk < 64; kk += 16) {
        unsigned af[2][4];
#pragma unroll
        for (int i = 0; i < 2; i++) {
            int r = wm + i * 16 + g;
            af[i][0] = *(const unsigned*)&As[r][kk + 2 * t];
            af[i][1] = *(const unsigned*)&As[r + 8][kk + 2 * t];
            af[i][2] = *(const unsigned*)&As[r][kk + 2 * t + 8];
            af[i][3] = *(const unsigned*)&As[r + 8][kk + 2 * t + 8];
        }
        unsigned bf[8][2];
#pragma unroll
        for (int j = 0; j < 8; j++) {
            int n = wn + j * 8 + g;
            bf[j][0] = *(const unsigned*)&Bs[n][kk + 2 * t];
            bf[j][1] = *(const unsigned*)&Bs[n][kk + 2 * t + 8];
        }
#pragma unroll
        for (int i = 0; i < 2; i++)
#pragma unroll
            for (int j = 0; j < 8; j++) {
                float* c = accf[i][j];
                asm volatile(
                    "mma.sync.aligned.m16n8k16.row.col.f32.f16.f16.f32 "
                    "{%0,%1,%2,%3}, {%4,%5,%6,%7}, {%8,%9}, {%0,%1,%2,%3};"
                    : "+f"(c[0]), "+f"(c[1]), "+f"(c[2]), "+f"(c[3])
                    : "r"(af[i][0]), "r"(af[i][1]), "r"(af[i][2]),
                      "r"(af[i][3]), "r"(bf[j][0]), "r"(bf[j][1]));
            }
    }
    __syncthreads();   // done reading As/Bs — safe to overwrite with Es

    // ---- phase 2: stage E tile into smem ----
#pragma unroll
    for (int i = 0; i < 2; i++) {
        int r0 = wm + i * 16 + g;
#pragma unroll
        for (int j = 0; j < 8; j++) {
            int col = wn + j * 8 + t * 2;
#pragma unroll
            for (int rr = 0; rr < 2; rr++)
                *(__half2*)&Es[r0 + rr * 8][col] = __floats2half2_rn(
                    accf[i][j][rr * 2 + 0], accf[i][j][rr * 2 + 1]);
        }
    }
    __syncthreads();

    // ---- phase 3: per-edge alpha + aggregation (warp per edge, 16 each) ----
#pragma unroll 4
    for (int u = 0; u < 16; u++) {
        int r = m0 + base + u;
        if (r >= cnt) break;
        int src = __shfl_sync(0xffffffffu, pf_sd, u);
        int dst = __shfl_sync(0xffffffffu, pf_sd, u + 16);
        uint2 eraw = *(const uint2*)&Es[base + u][lane * 4];
        uint2 qraw = *(const uint2*)&qh[(size_t)dst * 128 + lane * 4];
        uint4 kvraw = *(const uint4*)&kvh[(size_t)src * 256 + lane * 8];
        float2 e01 = __half22float2(*reinterpret_cast<__half2*>(&eraw.x));
        float2 e23 = __half22float2(*reinterpret_cast<__half2*>(&eraw.y));
        float2 q01 = __half22float2(*reinterpret_cast<__half2*>(&qraw.x));
        float2 q23 = __half22float2(*reinterpret_cast<__half2*>(&qraw.y));
        float2 kv0 = __half22float2(*reinterpret_cast<__half2*>(&kvraw.x));
        float2 kv1 = __half22float2(*reinterpret_cast<__half2*>(&kvraw.y));
        float2 kv2 = __half22float2(*reinterpret_cast<__half2*>(&kvraw.z));
        float2 kv3 = __half22float2(*reinterpret_cast<__half2*>(&kvraw.w));
        // kvN = (k_c, v_c) for channel c = lane*4 + N
        float p = q01.x * (kv0.x + e01.x) + q01.y * (kv1.x + e01.y) +
                  q23.x * (kv2.x + e23.x) + q23.y * (kv3.x + e23.y);
        p += __shfl_xor_sync(0xffffffffu, p, 1, 8);
        p += __shfl_xor_sync(0xffffffffu, p, 2, 8);
        p += __shfl_xor_sync(0xffffffffu, p, 4, 8);
        float a = __expf(p * 0.17677669529663687f);   // 1/sqrt(32)
        float ah1 = __shfl_sync(0xffffffffu, a, 8);
        float ah2 = __shfl_sync(0xffffffffu, a, 16);
        float ah3 = __shfl_sync(0xffffffffu, a, 24);
        if (lane == 0) {
            float* sp = &s[dst * 4];
            asm volatile("red.global.add.v4.f32 [%0], {%1,%2,%3,%4};"
                         :: "l"(sp), "f"(a), "f"(ah1), "f"(ah2), "f"(ah3)
                         : "memory");
        }
        float4 m = make_float4(a * (kv0.y + e01.x), a * (kv1.y + e01.y),
                               a * (kv2.y + e23.x), a * (kv3.y + e23.y));
        float* op = &acc[(size_t)dst * 128 + lane * 4];
        asm volatile("red.global.add.v4.f32 [%0], {%1,%2,%3,%4};"
                     :: "l"(op), "f"(m.x), "f"(m.y), "f"(m.z), "f"(m.w)
                     : "memory");
    }
}

// ------- normalize: out = skip + acc/s (+relu), fp16 out -------
__global__ void norm_kernel(const __half* __restrict__ skip,
                            const float* __restrict__ acc,
                            const float* __restrict__ s,
                            __half* __restrict__ outp, int nrows, int do_relu) {
    int idx = blockIdx.x * blockDim.x + threadIdx.x;
    if (idx >= nrows * 32) return;
    int n = idx >> 5, c4 = idx & 31;
    float inv = 1.f / (s[n * 4 + (c4 >> 3)] + 1e-16f);
    float4 a = *(const float4*)&acc[n * 128 + c4 * 4];
    uint2 sk = *(const uint2*)&skip[(size_t)n * 128 + c4 * 4];
    float2 s01 = __half22float2(*reinterpret_cast<__half2*>(&sk.x));
    float2 s23 = __half22float2(*reinterpret_cast<__half2*>(&sk.y));
    float4 o = make_float4(s01.x + a.x * inv, s01.y + a.y * inv,
                           s23.x + a.z * inv, s23.y + a.w * inv);
    if (do_relu) {
        o.x = fmaxf(o.x, 0.f); o.y = fmaxf(o.y, 0.f);
        o.z = fmaxf(o.z, 0.f); o.w = fmaxf(o.w, 0.f);
    }
    uint2 h;
    h.x = h2u(__floats2half2_rn(o.x, o.y));
    h.y = h2u(__floats2half2_rn(o.z, o.w));
    *(uint2*)&outp[(size_t)n * 128 + c4 * 4] = h;
}

// ---------------- final projection (fp16 x) ----------------
__global__ void proj_kernel(const __half* __restrict__ x,
                            const float* __restrict__ pW,
                            const float* __restrict__ pb,
                            float* __restrict__ y) {
    int row = blockIdx.x * 8 + (threadIdx.x >> 5);
    int lane = threadIdx.x & 31;
    if (row >= BATCH) return;
    float acc = pb[lane];
    const __half* xr = &x[(size_t)row * 128];
#pragma unroll 8
    for (int k = 0; k < 128; k++)
        acc += __half2float(xr[k]) * pW[k * 32 + lane];
    y[row * 32 + lane] = acc;
}

// ---------------- host launch ----------------
extern "C" void kernel_launch(void* const* d_in, const int* in_sizes, int n_in,
                              void* d_out, int out_size) {
    int off = (n_in >= 28) ? 1 : 0;
    const int* n_id       = (const int*)d_in[0];
    const int* ei         = (const int*)d_in[1];
    const float* times    = (const float*)d_in[2];
    const float* feats    = (const float*)d_in[3];
    const float* node_emb = (const float*)d_in[4 + off];
    const float* tw       = (const float*)d_in[5 + off];
    const float* tb       = (const float*)d_in[6 + off];
    const float* q1W = (const float*)d_in[7 + off],  *q1b = (const float*)d_in[8 + off];
    const float* k1W = (const float*)d_in[9 + off],  *k1b = (const float*)d_in[10 + off];
    const float* v1W = (const float*)d_in[11 + off], *v1b = (const float*)d_in[12 + off];
    const float* e1W = (const float*)d_in[13 + off];
    const float* s1W = (const float*)d_in[14 + off], *s1b = (const float*)d_in[15 + off];
    const float* q2W = (const float*)d_in[16 + off], *q2b = (const float*)d_in[17 + off];
    const float* k2W = (const float*)d_in[18 + off], *k2b = (const float*)d_in[19 + off];
    const float* v2W = (const float*)d_in[20 + off], *v2b = (const float*)d_in[21 + off];
    const float* e2W = (const float*)d_in[22 + off];
    const float* s2W = (const float*)d_in[23 + off], *s2b = (const float*)d_in[24 + off];
    const float* pW  = (const float*)d_in[25 + off], *pb  = (const float*)d_in[26 + off];

    float *p_accs, *p_bc0, *p_bc1;
    __half *p_xh, *p_qh, *p_kvh, *p_skip, *p_h2, *p_Wch0, *p_Wch1, *p_Weh0, *p_Weh1;
    int *p_eidx, *p_cnt;
    cudaGetSymbolAddress((void**)&p_xh, g_xh);
    cudaGetSymbolAddress((void**)&p_qh, g_qh);
    cudaGetSymbolAddress((void**)&p_kvh, g_kvh);
    cudaGetSymbolAddress((void**)&p_skip, g_skiph);
    cudaGetSymbolAddress((void**)&p_accs, g_accs);
    cudaGetSymbolAddress((void**)&p_h2, g_h2);
    cudaGetSymbolAddress((void**)&p_Wch0, g_Wch);
    p_Wch1 = p_Wch0 + 512 * 128;
    cudaGetSymbolAddress((void**)&p_bc0, g_bc);
    p_bc1 = p_bc0 + 512;
    cudaGetSymbolAddress((void**)&p_Weh0, g_Weh);
    p_Weh1 = p_Weh0 + 128 * 64;
    cudaGetSymbolAddress((void**)&p_eidx, g_eidx);
    cudaGetSymbolAddress((void**)&p_cnt, g_cnt);

    float* p_acc = p_accs;                     // NN*128
    float* p_s   = p_accs + (size_t)NN * 128;  // NN*4

    const int GB_N = (NN + 127) / 128;      // 391
    const int GB_B = (BATCH + 127) / 128;   // 79
    const int GB_E = (NE + 127) / 128;      // 3907
    const int GB_E2 = 977;                  // covers cnt up to 125k edges
    const int PROLOGUE_BLKS = PB_CONCAT + PB_PREP + PB_GATHER + PB_COMPACT;

    // ----- prologue -----
    cudaMemsetAsync(p_cnt, 0, sizeof(int));
    prologue<<<PROLOGUE_BLKS, 256>>>(n_id, node_emb, ei,
                                     q1W, k1W, v1W, s1W, q1b, k1b, v1b, s1b,
                                     q2W, k2W, v2W, s2W, q2b, k2b, v2b, s2b,
                                     e1W, e2W);

    // ----- layer 1 (all nodes, all edges) -----
    node_gemm_h<<<dim3(GB_N, 4), 256>>>(p_xh, p_Wch0, p_bc0, p_qh, p_kvh, p_skip);
    cudaMemsetAsync(p_accs, 0, (size_t)NN * 132 * sizeof(float));
    edge_fused<<<GB_E, 256>>>(feats, times, tw, tb, p_Weh0, nullptr, nullptr, NE,
                              ei, p_qh, p_kvh, p_s, p_acc);
    norm_kernel<<<(NN * 32 + 255) / 256, 256>>>(p_skip, p_acc, p_s, p_xh, NN, 1);

    // ----- layer 2 (only dst < BATCH matters) -----
    node_gemm_l2<<<GB_B + 2 * GB_N + GB_B, 256>>>(p_xh, p_Wch1, p_bc1, p_qh,
                                                  p_kvh, p_skip);
    cudaMemsetAsync(p_acc, 0, (size_t)BATCH * 128 * sizeof(float));
    cudaMemsetAsync(p_s, 0, BATCH * 4 * sizeof(float));
    edge_fused<<<GB_E2, 256>>>(feats, times, tw, tb, p_Weh1, p_eidx, p_cnt, 0,
                               ei, p_qh, p_kvh, p_s, p_acc);
    norm_kernel<<<(BATCH * 32 + 255) / 256, 256>>>(p_skip, p_acc, p_s, p_h2,
                                                   BATCH, 0);

    // ----- projection -----
    proj_kernel<<<(BATCH + 7) / 8, 256>>>(p_h2, pW, pb, (float*)d_out);
}

// round 16
// speedup vs baseline: 1.0972x; 1.0972x over previous
#include <cuda_runtime.h>
#include <cuda_fp16.h>
#include <math.h>

#define NN 50000
#define NE 500000
#define BATCH 10000

// ---------------- scratch ----------------
__device__ __half g_xh[NN * 128];       // fp16 node features (GEMM input)
__device__ __half g_qkvh[NN * 384];     // fp16 [q|k|v]
__device__ __half g_skiph[NN * 128];    // fp16 skip
__device__ float  g_accs[NN * 132];     // [acc NN*128 | s NN*4] one memset
__device__ __half g_Wch[2][512 * 128];  // concat weights, n-major fp16 (both layers)
__device__ float  g_bc[2][512];
__device__ __half g_Weh[2][128 * 64];   // edge weights, n-major fp16 (both layers)
__device__ int    g_eidx[NE];
__device__ int    g_cnt;

__device__ __forceinline__ unsigned h2u(__half2 h) {
    unsigned u;
    *reinterpret_cast<__half2*>(&u) = h;
    return u;
}

__device__ __forceinline__ void cp16(void* smem, const void* gmem, bool pred) {
    unsigned sa = (unsigned)__cvta_generic_to_shared(smem);
    int sz = pred ? 16 : 0;
    asm volatile("cp.async.cg.shared.global [%0], [%1], 16, %2;"
                 :: "r"(sa), "l"(gmem), "r"(sz) : "memory");
}

// ============ PROLOGUE mega-kernel: compact | gather | concat_w | prep_we ===
#define PB_CONCAT 128
#define PB_PREP   64
#define PB_GATHER 3125
#define PB_COMPACT 1954

__global__ __launch_bounds__(256) void prologue(
    const int* __restrict__ n_id, const float* __restrict__ emb,
    const int* __restrict__ ei,
    const float* __restrict__ qW1, const float* __restrict__ kW1,
    const float* __restrict__ vW1, const float* __restrict__ sW1,
    const float* __restrict__ qb1, const float* __restrict__ kb1,
    const float* __restrict__ vb1, const float* __restrict__ sb1,
    const float* __restrict__ qW2, const float* __restrict__ kW2,
    const float* __restrict__ vW2, const float* __restrict__ sW2,
    const float* __restrict__ qb2, const float* __restrict__ kb2,
    const float* __restrict__ vb2, const float* __restrict__ sb2,
    const float* __restrict__ We1, const float* __restrict__ We2) {
    __shared__ float tile[32][33];
    const int bx = blockIdx.x;
    const int tid = threadIdx.x;

    if (bx < PB_CONCAT) {
        const float* Ws[8] = {qW1, kW1, vW1, sW1, qW2, kW2, vW2, sW2};
        const float* bs[8] = {qb1, kb1, vb1, sb1, qb2, kb2, vb2, sb2};
        int id = bx >> 4;
        int ky = (bx >> 2) & 3, cz = bx & 3;
        int layer = id >> 2, which = id & 3;
        int k0 = ky * 32, c0 = cz * 32;
        const float* W = Ws[id];
        int tx = tid & 31, ty = tid >> 5;
#pragma unroll
        for (int i = 0; i < 4; i++)
            tile[ty + i * 8][tx] = W[(k0 + ty + i * 8) * 128 + c0 + tx];
        __syncthreads();
#pragma unroll
        for (int i = 0; i < 4; i++) {
            int c = c0 + ty + i * 8;
            g_Wch[layer][(which * 128 + c) * 128 + k0 + tx] =
                __float2half(tile[tx][ty + i * 8]);
        }
        if (ky == 0 && ty == 0)
            g_bc[layer][which * 128 + c0 + tx] = bs[id][c0 + tx];
    } else if (bx < PB_CONCAT + PB_PREP) {
        int i = (bx - PB_CONCAT) * 256 + tid;
        int layer = i >= 64 * 128;
        int j = i - layer * 64 * 128;
        int k = j >> 7, n = j & 127;
        const float* We = layer ? We2 : We1;
        g_Weh[layer][n * 64 + k] = __float2half(We[j]);
    } else if (bx < PB_CONCAT + PB_PREP + PB_GATHER) {
        int idx = (bx - PB_CONCAT - PB_PREP) * 256 + tid;
        int i = idx >> 4;
        int c = (idx & 15) * 8;
        const float4* src = (const float4*)&emb[(size_t)n_id[i] * 128 + c];
        float4 v0 = src[0], v1 = src[1];
        uint4 o;
        o.x = h2u(__floats2half2_rn(v0.x, v0.y));
        o.y = h2u(__floats2half2_rn(v0.z, v0.w));
        o.z = h2u(__floats2half2_rn(v1.x, v1.y));
        o.w = h2u(__floats2half2_rn(v1.z, v1.w));
        *(uint4*)&g_xh[i * 128 + c] = o;
    } else {
        int e = (bx - PB_CONCAT - PB_PREP - PB_GATHER) * 256 + tid;
        if (e < NE && ei[NE + e] < BATCH) {
            int slot = atomicAdd(&g_cnt, 1);
            g_eidx[slot] = e;
        }
    }
}

// ---------------- shared GEMM tile body (fp16 m16n8k16, cp.async 2-stage) ---
__device__ __forceinline__ void gemm_tile_body(
    const __half* __restrict__ A, const __half* __restrict__ W,
    const float* __restrict__ bias, __half* __restrict__ Cq,
    __half* __restrict__ Cs, int M, int m0, int n0) {
    __shared__ __half As[2][128][40];
    __shared__ __half Bs[2][128][40];
    const int tid = threadIdx.x;
    const int lane = tid & 31, wid = tid >> 5;
    const int wm = (wid & 3) * 32, wn = (wid >> 2) * 64;
    const int g = lane >> 2, t = lane & 3;
    const int lrow = tid >> 1;
    const int lcol = (tid & 1) * 16;
    const int gr = m0 + lrow;
    const bool aval = gr < M;
    const __half* abase = &A[(size_t)(aval ? gr : 0) * 128 + lcol];
    const __half* bbase = &W[(size_t)(n0 + lrow) * 128 + lcol];

    float acc[2][8][4];
#pragma unroll
    for (int i = 0; i < 2; i++)
#pragma unroll
        for (int j = 0; j < 8; j++)
#pragma unroll
            for (int c = 0; c < 4; c++) acc[i][j][c] = 0.f;

#pragma unroll
    for (int it = 0; it < 2; it++) {
        int k0 = it * 32;
        cp16(&As[it][lrow][lcol],     abase + k0, aval);
        cp16(&As[it][lrow][lcol + 8], abase + k0 + 8, aval);
        cp16(&Bs[it][lrow][lcol],     bbase + k0, true);
        cp16(&Bs[it][lrow][lcol + 8], bbase + k0 + 8, true);
        asm volatile("cp.async.commit_group;" ::: "memory");
    }

#pragma unroll
    for (int it = 0; it < 4; it++) {
        if (it < 3)
            asm volatile("cp.async.wait_group 1;" ::: "memory");
        else
            asm volatile("cp.async.wait_group 0;" ::: "memory");
        __syncthreads();
        const int buf = it & 1;
#pragma unroll
        for (int kk = 0; kk < 32; kk += 16) {
            unsigned af[2][4];
#pragma unroll
            for (int i = 0; i < 2; i++) {
                int r = wm + i * 16 + g;
                af[i][0] = *(const unsigned*)&As[buf][r][kk + 2 * t];
                af[i][1] = *(const unsigned*)&As[buf][r + 8][kk + 2 * t];
                af[i][2] = *(const unsigned*)&As[buf][r][kk + 2 * t + 8];
                af[i][3] = *(const unsigned*)&As[buf][r + 8][kk + 2 * t + 8];
            }
            unsigned bf[8][2];
#pragma unroll
            for (int j = 0; j < 8; j++) {
                int n = wn + j * 8 + g;
                bf[j][0] = *(const unsigned*)&Bs[buf][n][kk + 2 * t];
                bf[j][1] = *(const unsigned*)&Bs[buf][n][kk + 2 * t + 8];
            }
#pragma unroll
            for (int i = 0; i < 2; i++)
#pragma unroll
                for (int j = 0; j < 8; j++) {
                    float* c = acc[i][j];
                    asm volatile(
                        "mma.sync.aligned.m16n8k16.row.col.f32.f16.f16.f32 "
                        "{%0,%1,%2,%3}, {%4,%5,%6,%7}, {%8,%9}, {%0,%1,%2,%3};"
                        : "+f"(c[0]), "+f"(c[1]), "+f"(c[2]), "+f"(c[3])
                        : "r"(af[i][0]), "r"(af[i][1]), "r"(af[i][2]),
                          "r"(af[i][3]), "r"(bf[j][0]), "r"(bf[j][1]));
                }
        }
        __syncthreads();
        if (it + 2 < 4) {
            int k0 = (it + 2) * 32;
            cp16(&As[buf][lrow][lcol],     abase + k0, aval);
            cp16(&As[buf][lrow][lcol + 8], abase + k0 + 8, aval);
            cp16(&Bs[buf][lrow][lcol],     bbase + k0, true);
            cp16(&Bs[buf][lrow][lcol + 8], bbase + k0 + 8, true);
            asm volatile("cp.async.commit_group;" ::: "memory");
        }
    }
#pragma unroll
    for (int i = 0; i < 2; i++) {
        int r0 = m0 + wm + i * 16 + g;
#pragma unroll
        for (int j = 0; j < 8; j++) {
            int col = n0 + wn + j * 8 + t * 2;
            float b0 = bias[col], b1 = bias[col + 1];
#pragma unroll
            for (int rr = 0; rr < 2; rr++) {
                int row = r0 + rr * 8;
                if (row < M) {
                    float o0 = acc[i][j][rr * 2 + 0] + b0;
                    float o1 = acc[i][j][rr * 2 + 1] + b1;
                    if (col < 384) {
                        *(__half2*)&Cq[(size_t)row * 384 + col] =
                            __floats2half2_rn(o0, o1);
                    } else {
                        *(__half2*)&Cs[(size_t)row * 128 + col - 384] =
                            __floats2half2_rn(o0, o1);
                    }
                }
            }
        }
    }
}

// layer-1 node GEMM: grid (391, 4)
__global__ __launch_bounds__(256) void node_gemm_h(
    const __half* __restrict__ A, const __half* __restrict__ W,
    const float* __restrict__ bias, __half* __restrict__ Cq,
    __half* __restrict__ Cs) {
    gemm_tile_body(A, W, bias, Cq, Cs, NN, blockIdx.x * 128, blockIdx.y * 128);
}

// layer-2 node GEMM, single launch: q(BATCH) | k,v(NN) | s(BATCH)
__global__ __launch_bounds__(256) void node_gemm_l2(
    const __half* __restrict__ A, const __half* __restrict__ W,
    const float* __restrict__ bias, __half* __restrict__ Cq,
    __half* __restrict__ Cs) {
    const int GB_B = (BATCH + 127) / 128;   // 79
    const int GB_N = (NN + 127) / 128;      // 391
    int bx = blockIdx.x;
    int m0, n0, M;
    if (bx < GB_B) {
        m0 = bx * 128; n0 = 0; M = BATCH;
    } else if (bx < GB_B + 2 * GB_N) {
        int idx = bx - GB_B;
        m0 = (idx % GB_N) * 128; n0 = 128 + (idx / GB_N) * 128; M = NN;
    } else {
        m0 = (bx - GB_B - 2 * GB_N) * 128; n0 = 384; M = BATCH;
    }
    gemm_tile_body(A, W, bias, Cq, Cs, M, m0, n0);
}

// ===== FUSED edge kernel: attr build + E GEMM (smem) + alpha/agg atomics =====
__global__ __launch_bounds__(256) void edge_fused(
    const float* __restrict__ feats, const float* __restrict__ times,
    const float* __restrict__ tw, const float* __restrict__ tb,
    const __half* __restrict__ Weh,
    const int* __restrict__ eidx, const int* __restrict__ cntp, int cnt_c,
    const int* __restrict__ ei, const __half* __restrict__ qkv,
    float* __restrict__ s, float* __restrict__ acc) {
    const int cnt = cntp ? *cntp : cnt_c;
    const int m0 = blockIdx.x * 128;
    if (m0 >= cnt) return;

    __shared__ __align__(16) char sbuf[36864];
    __half (*As)[72] = (__half(*)[72])sbuf;                 // [128][72]
    __half (*Bs)[72] = (__half(*)[72])(sbuf + 18432);       // [128][72]
    __half (*Es)[136] = (__half(*)[136])sbuf;               // overlaps (phase 2+)

    const int tid = threadIdx.x;
    const int lane = tid & 31, wid = tid >> 5;
    const int wm = (wid & 3) * 32, wn = (wid >> 2) * 64;
    const int g = lane >> 2, t = lane & 3;

    float accf[2][8][4];
#pragma unroll
    for (int i = 0; i < 2; i++)
#pragma unroll
        for (int j = 0; j < 8; j++)
#pragma unroll
            for (int c = 0; c < 4; c++) accf[i][j][c] = 0.f;

    // ---- phase 1: build A (edge attr) + B (We) tiles ----
    const int lrow = tid >> 1;
    const int hs = tid & 1;
    {
        int r = m0 + lrow;
        bool valid = r < cnt;
        int eid = valid ? (eidx ? eidx[r] : r) : 0;
        if (hs == 0) {   // feats cols 0..31
#pragma unroll
            for (int c = 0; c < 4; c++) {
                float4 v0, v1;
                if (valid) {
                    const float4* fp = (const float4*)&feats[(size_t)eid * 32 + c * 8];
                    v0 = fp[0]; v1 = fp[1];
                } else {
                    v0 = v1 = make_float4(0.f, 0.f, 0.f, 0.f);
                }
                uint4 o;
                o.x = h2u(__floats2half2_rn(v0.x, v0.y));
                o.y = h2u(__floats2half2_rn(v0.z, v0.w));
                o.z = h2u(__floats2half2_rn(v1.x, v1.y));
                o.w = h2u(__floats2half2_rn(v1.z, v1.w));
                *(uint4*)&As[lrow][c * 8] = o;
            }
        } else {         // time-embedding cols 32..63
            float tv = valid ? times[eid] : 0.f;
#pragma unroll
            for (int c = 0; c < 4; c++) {
                float cv[8];
#pragma unroll
                for (int u = 0; u < 8; u++) {
                    int j = c * 8 + u;
                    cv[u] = __cosf(tv * __ldg(&tw[j]) + __ldg(&tb[j]));
                }
                uint4 o;
                o.x = h2u(__floats2half2_rn(cv[0], cv[1]));
                o.y = h2u(__floats2half2_rn(cv[2], cv[3]));
                o.z = h2u(__floats2half2_rn(cv[4], cv[5]));
                o.w = h2u(__floats2half2_rn(cv[6], cv[7]));
                *(uint4*)&As[lrow][32 + c * 8] = o;
            }
        }
        const uint4* bp = (const uint4*)&Weh[lrow * 64 + hs * 32];
        uint4* bd = (uint4*)&Bs[lrow][hs * 32];
        bd[0] = bp[0]; bd[1] = bp[1]; bd[2] = bp[2]; bd[3] = bp[3];
    }

    // ---- prefetch src/dst for this warp's 16 edges (coalesced, pre-sync) ----
    const int base = wid * 16;
    int pf_sd;
    {
        int u = lane & 15;
        int r = m0 + base + u;
        int rr = r < cnt ? r : cnt - 1;
        int eid = eidx ? __ldg(&eidx[rr]) : rr;
        pf_sd = (lane < 16) ? __ldg(&ei[eid]) : __ldg(&ei[NE + eid]);
    }
    __syncthreads();

    // ---- MMA over K=64 ----
#pragma unroll
    for (int kk = 0; kk < 64; kk += 16) {
        unsigned af[2][4];
#pragma unroll
        for (int i = 0; i < 2; i++) {
            int r = wm + i * 16 + g;
            af[i][0] = *(const unsigned*)&As[r][kk + 2 * t];
            af[i][1] = *(const unsigned*)&As[r + 8][kk + 2 * t];
            af[i][2] = *(const unsigned*)&As[r][kk + 2 * t + 8];
            af[i][3] = *(const unsigned*)&As[r + 8][kk + 2 * t + 8];
        }
        unsigned bf[8][2];
#pragma unroll
        for (int j = 0; j < 8; j++) {
            int n = wn + j * 8 + g;
            bf[j][0] = *(const unsigned*)&Bs[n][kk + 2 * t];
            bf[j][1] = *(const unsigned*)&Bs[n][kk + 2 * t + 8];
        }
#pragma unroll
        for (int i = 0; i < 2; i++)
#pragma unroll
            for (int j = 0; j < 8; j++) {
                float* c = accf[i][j];
                asm volatile(
                    "mma.sync.aligned.m16n8k16.row.col.f32.f16.f16.f32 "
                    "{%0,%1,%2,%3}, {%4,%5,%6,%7}, {%8,%9}, {%0,%1,%2,%3};"
                    : "+f"(c[0]), "+f"(c[1]), "+f"(c[2]), "+f"(c[3])
                    : "r"(af[i][0]), "r"(af[i][1]), "r"(af[i][2]),
                      "r"(af[i][3]), "r"(bf[j][0]), "r"(bf[j][1]));
            }
    }
    __syncthreads();   // done reading As/Bs — safe to overwrite with Es

    // ---- phase 2: stage E tile into smem ----
#pragma unroll
    for (int i = 0; i < 2; i++) {
        int r0 = wm + i * 16 + g;
#pragma unroll
        for (int j = 0; j < 8; j++) {
            int col = wn + j * 8 + t * 2;
#pragma unroll
            for (int rr = 0; rr < 2; rr++)
                *(__half2*)&Es[r0 + rr * 8][col] = __floats2half2_rn(
                    accf[i][j][rr * 2 + 0], accf[i][j][rr * 2 + 1]);
        }
    }
    __syncthreads();

    // ---- phase 3: per-edge alpha + aggregation (warp per edge, 16 each) ----
#pragma unroll 4
    for (int u = 0; u < 16; u++) {
        int r = m0 + base + u;
        if (r >= cnt) break;
        int src = __shfl_sync(0xffffffffu, pf_sd, u);
        int dst = __shfl_sync(0xffffffffu, pf_sd, u + 16);
        uint2 eraw = *(const uint2*)&Es[base + u][lane * 4];
        uint2 qraw = *(const uint2*)&qkv[(size_t)dst * 384 + lane * 4];
        uint2 kraw = *(const uint2*)&qkv[(size_t)src * 384 + 128 + lane * 4];
        uint2 vraw = *(const uint2*)&qkv[(size_t)src * 384 + 256 + lane * 4];
        float2 e01 = __half22float2(*reinterpret_cast<__half2*>(&eraw.x));
        float2 e23 = __half22float2(*reinterpret_cast<__half2*>(&eraw.y));
        float2 q01 = __half22float2(*reinterpret_cast<__half2*>(&qraw.x));
        float2 q23 = __half22float2(*reinterpret_cast<__half2*>(&qraw.y));
        float2 k01 = __half22float2(*reinterpret_cast<__half2*>(&kraw.x));
        float2 k23 = __half22float2(*reinterpret_cast<__half2*>(&kraw.y));
        float2 v01 = __half22float2(*reinterpret_cast<__half2*>(&vraw.x));
        float2 v23 = __half22float2(*reinterpret_cast<__half2*>(&vraw.y));
        float p = q01.x * (k01.x + e01.x) + q01.y * (k01.y + e01.y) +
                  q23.x * (k23.x + e23.x) + q23.y * (k23.y + e23.y);
        p += __shfl_xor_sync(0xffffffffu, p, 1, 8);
        p += __shfl_xor_sync(0xffffffffu, p, 2, 8);
        p += __shfl_xor_sync(0xffffffffu, p, 4, 8);
        float a = __expf(p * 0.17677669529663687f);   // 1/sqrt(32)
        float ah1 = __shfl_sync(0xffffffffu, a, 8);
        float ah2 = __shfl_sync(0xffffffffu, a, 16);
        float ah3 = __shfl_sync(0xffffffffu, a, 24);
        if (lane == 0) {
            float* sp = &s[dst * 4];
            asm volatile("red.global.add.v4.f32 [%0], {%1,%2,%3,%4};"
                         :: "l"(sp), "f"(a), "f"(ah1), "f"(ah2), "f"(ah3)
                         : "memory");
        }
        float4 m = make_float4(a * (v01.x + e01.x), a * (v01.y + e01.y),
                               a * (v23.x + e23.x), a * (v23.y + e23.y));
        float* op = &acc[(size_t)dst * 128 + lane * 4];
        asm volatile("red.global.add.v4.f32 [%0], {%1,%2,%3,%4};"
                     :: "l"(op), "f"(m.x), "f"(m.y), "f"(m.z), "f"(m.w)
                     : "memory");
    }
}

// ------- layer-1 normalize: out = relu(skip + acc/s) -> fp16 -------
__global__ void norm_kernel(const __half* __restrict__ skip,
                            const float* __restrict__ acc,
                            const float* __restrict__ s,
                            __half* __restrict__ outp) {
    int idx = blockIdx.x * blockDim.x + threadIdx.x;
    if (idx >= NN * 32) return;
    int n = idx >> 5, c4 = idx & 31;
    float inv = 1.f / (s[n * 4 + (c4 >> 3)] + 1e-16f);
    float4 a = *(const float4*)&acc[n * 128 + c4 * 4];
    uint2 sk = *(const uint2*)&skip[(size_t)n * 128 + c4 * 4];
    float2 s01 = __half22float2(*reinterpret_cast<__half2*>(&sk.x));
    float2 s23 = __half22float2(*reinterpret_cast<__half2*>(&sk.y));
    float4 o = make_float4(fmaxf(s01.x + a.x * inv, 0.f),
                           fmaxf(s01.y + a.y * inv, 0.f),
                           fmaxf(s23.x + a.z * inv, 0.f),
                           fmaxf(s23.y + a.w * inv, 0.f));
    uint2 h;
    h.x = h2u(__floats2half2_rn(o.x, o.y));
    h.y = h2u(__floats2half2_rn(o.z, o.w));
    *(uint2*)&outp[(size_t)n * 128 + c4 * 4] = h;
}

// ------- layer-2 normalize + projection fused: y = (skip + acc/s) @ pW + pb --
// block = 256 thr = 8 warps; warp per row
__global__ __launch_bounds__(256) void norm_proj_kernel(
    const __half* __restrict__ skip, const float* __restrict__ acc,
    const float* __restrict__ s, const float* __restrict__ pW,
    const float* __restrict__ pb, float* __restrict__ y) {
    __shared__ float xrow[8][128];
    int wid = threadIdx.x >> 5, lane = threadIdx.x & 31;
    int row = blockIdx.x * 8 + wid;
    if (row >= BATCH) return;
    // normalize: each lane handles 4 channels
    float inv = 1.f / (s[row * 4 + (lane >> 3)] + 1e-16f);
    float4 a = *(const float4*)&acc[(size_t)row * 128 + lane * 4];
    uint2 sk = *(const uint2*)&skip[(size_t)row * 128 + lane * 4];
    float2 s01 = __half22float2(*reinterpret_cast<__half2*>(&sk.x));
    float2 s23 = __half22float2(*reinterpret_cast<__half2*>(&sk.y));
    xrow[wid][lane * 4 + 0] = s01.x + a.x * inv;
    xrow[wid][lane * 4 + 1] = s01.y + a.y * inv;
    xrow[wid][lane * 4 + 2] = s23.x + a.z * inv;
    xrow[wid][lane * 4 + 3] = s23.y + a.w * inv;
    __syncwarp();
    float accv = pb[lane];
#pragma unroll 8
    for (int k = 0; k < 128; k++)
        accv += xrow[wid][k] * pW[k * 32 + lane];
    y[row * 32 + lane] = accv;
}

// ---------------- host launch ----------------
extern "C" void kernel_launch(void* const* d_in, const int* in_sizes, int n_in,
                              void* d_out, int out_size) {
    int off = (n_in >= 28) ? 1 : 0;
    const int* n_id       = (const int*)d_in[0];
    const int* ei         = (const int*)d_in[1];
    const float* times    = (const float*)d_in[2];
    const float* feats    = (const float*)d_in[3];
    const float* node_emb = (const float*)d_in[4 + off];
    const float* tw       = (const float*)d_in[5 + off];
    const float* tb       = (const float*)d_in[6 + off];
    const float* q1W = (const float*)d_in[7 + off],  *q1b = (const float*)d_in[8 + off];
    const float* k1W = (const float*)d_in[9 + off],  *k1b = (const float*)d_in[10 + off];
    const float* v1W = (const float*)d_in[11 + off], *v1b = (const float*)d_in[12 + off];
    const float* e1W = (const float*)d_in[13 + off];
    const float* s1W = (const float*)d_in[14 + off], *s1b = (const float*)d_in[15 + off];
    const float* q2W = (const float*)d_in[16 + off], *q2b = (const float*)d_in[17 + off];
    const float* k2W = (const float*)d_in[18 + off], *k2b = (const float*)d_in[19 + off];
    const float* v2W = (const float*)d_in[20 + off], *v2b = (const float*)d_in[21 + off];
    const float* e2W = (const float*)d_in[22 + off];
    const float* s2W = (const float*)d_in[23 + off], *s2b = (const float*)d_in[24 + off];
    const float* pW  = (const float*)d_in[25 + off], *pb  = (const float*)d_in[26 + off];

    float *p_accs, *p_bc0, *p_bc1;
    __half *p_xh, *p_qkv, *p_skip, *p_Wch0, *p_Wch1, *p_Weh0, *p_Weh1;
    int *p_eidx, *p_cnt;
    cudaGetSymbolAddress((void**)&p_xh, g_xh);
    cudaGetSymbolAddress((void**)&p_qkv, g_qkvh);
    cudaGetSymbolAddress((void**)&p_skip, g_skiph);
    cudaGetSymbolAddress((void**)&p_accs, g_accs);
    cudaGetSymbolAddress((void**)&p_Wch0, g_Wch);
    p_Wch1 = p_Wch0 + 512 * 128;
    cudaGetSymbolAddress((void**)&p_bc0, g_bc);
    p_bc1 = p_bc0 + 512;
    cudaGetSymbolAddress((void**)&p_Weh0, g_Weh);
    p_Weh1 = p_Weh0 + 128 * 64;
    cudaGetSymbolAddress((void**)&p_eidx, g_eidx);
    cudaGetSymbolAddress((void**)&p_cnt, g_cnt);

    float* p_acc = p_accs;                     // NN*128
    float* p_s   = p_accs + (size_t)NN * 128;  // NN*4

    const int GB_N = (NN + 127) / 128;      // 391
    const int GB_B = (BATCH + 127) / 128;   // 79
    const int GB_E = (NE + 127) / 128;      // 3907
    const int GB_E2 = 977;                  // covers cnt up to 125k edges
    const int PROLOGUE_BLKS = PB_CONCAT + PB_PREP + PB_GATHER + PB_COMPACT;

    // ----- prologue -----
    cudaMemsetAsync(p_cnt, 0, sizeof(int));
    prologue<<<PROLOGUE_BLKS, 256>>>(n_id, node_emb, ei,
                                     q1W, k1W, v1W, s1W, q1b, k1b, v1b, s1b,
                                     q2W, k2W, v2W, s2W, q2b, k2b, v2b, s2b,
                                     e1W, e2W);

    // ----- layer 1 (all nodes, all edges) -----
    node_gemm_h<<<dim3(GB_N, 4), 256>>>(p_xh, p_Wch0, p_bc0, p_qkv, p_skip);
    cudaMemsetAsync(p_accs, 0, (size_t)NN * 132 * sizeof(float));
    edge_fused<<<GB_E, 256>>>(feats, times, tw, tb, p_Weh0, nullptr, nullptr, NE,
                              ei, p_qkv, p_s, p_acc);
    norm_kernel<<<(NN * 32 + 255) / 256, 256>>>(p_skip, p_acc, p_s, p_xh);

    // ----- layer 2 (only dst < BATCH matters) -----
    node_gemm_l2<<<GB_B + 2 * GB_N + GB_B, 256>>>(p_xh, p_Wch1, p_bc1, p_qkv,
                                                  p_skip);
    cudaMemsetAsync(p_acc, 0, (size_t)BATCH * 128 * sizeof(float));
    cudaMemsetAsync(p_s, 0, BATCH * 4 * sizeof(float));
    edge_fused<<<GB_E2, 256>>>(feats, times, tw, tb, p_Weh1, p_eidx, p_cnt, 0,
                               ei, p_qkv, p_s, p_acc);
    norm_proj_kernel<<<(BATCH + 7) / 8, 256>>>(p_skip, p_acc, p_s, pW, pb,
                                               (float*)d_out);
}

// round 17
// speedup vs baseline: 1.1990x; 1.0928x over previous
#include <cuda_runtime.h>
#include <cuda_fp16.h>
#include <math.h>

#define NN 50000
#define NE 500000
#define BATCH 10000

// ---------------- scratch ----------------
__device__ __half g_xh[NN * 128];       // fp16 node features (GEMM input)
__device__ __half g_qkvh[NN * 384];     // fp16 [q|k|v]
__device__ __half g_skiph[NN * 128];    // fp16 skip
__device__ float  g_accs[NN * 132];     // [acc NN*128 | s NN*4] one memset
__device__ __half g_Wch[2][512 * 128];  // concat weights, n-major fp16 (both layers)
__device__ float  g_bc[2][512];
__device__ __half g_Weh[2][128 * 64];   // edge weights, n-major fp16 (both layers)
__device__ int    g_eidx[NE];
__device__ int    g_cnt;

__device__ __forceinline__ unsigned h2u(__half2 h) {
    unsigned u;
    *reinterpret_cast<__half2*>(&u) = h;
    return u;
}

__device__ __forceinline__ void cp16(void* smem, const void* gmem, bool pred) {
    unsigned sa = (unsigned)__cvta_generic_to_shared(smem);
    int sz = pred ? 16 : 0;
    asm volatile("cp.async.cg.shared.global [%0], [%1], 16, %2;"
                 :: "r"(sa), "l"(gmem), "r"(sz) : "memory");
}

// ============ PROLOGUE mega-kernel: compact | gather | concat_w | prep_we ===
#define PB_CONCAT 128
#define PB_PREP   64
#define PB_GATHER 3125
#define PB_COMPACT 1954

__global__ __launch_bounds__(256) void prologue(
    const int* __restrict__ n_id, const float* __restrict__ emb,
    const int* __restrict__ ei,
    const float* __restrict__ qW1, const float* __restrict__ kW1,
    const float* __restrict__ vW1, const float* __restrict__ sW1,
    const float* __restrict__ qb1, const float* __restrict__ kb1,
    const float* __restrict__ vb1, const float* __restrict__ sb1,
    const float* __restrict__ qW2, const float* __restrict__ kW2,
    const float* __restrict__ vW2, const float* __restrict__ sW2,
    const float* __restrict__ qb2, const float* __restrict__ kb2,
    const float* __restrict__ vb2, const float* __restrict__ sb2,
    const float* __restrict__ We1, const float* __restrict__ We2) {
    __shared__ float tile[32][33];
    const int bx = blockIdx.x;
    const int tid = threadIdx.x;

    if (bx < PB_CONCAT) {
        const float* Ws[8] = {qW1, kW1, vW1, sW1, qW2, kW2, vW2, sW2};
        const float* bs[8] = {qb1, kb1, vb1, sb1, qb2, kb2, vb2, sb2};
        int id = bx >> 4;
        int ky = (bx >> 2) & 3, cz = bx & 3;
        int layer = id >> 2, which = id & 3;
        int k0 = ky * 32, c0 = cz * 32;
        const float* W = Ws[id];
        int tx = tid & 31, ty = tid >> 5;
#pragma unroll
        for (int i = 0; i < 4; i++)
            tile[ty + i * 8][tx] = W[(k0 + ty + i * 8) * 128 + c0 + tx];
        __syncthreads();
#pragma unroll
        for (int i = 0; i < 4; i++) {
            int c = c0 + ty + i * 8;
            g_Wch[layer][(which * 128 + c) * 128 + k0 + tx] =
                __float2half(tile[tx][ty + i * 8]);
        }
        if (ky == 0 && ty == 0)
            g_bc[layer][which * 128 + c0 + tx] = bs[id][c0 + tx];
    } else if (bx < PB_CONCAT + PB_PREP) {
        int i = (bx - PB_CONCAT) * 256 + tid;
        int layer = i >= 64 * 128;
        int j = i - layer * 64 * 128;
        int k = j >> 7, n = j & 127;
        const float* We = layer ? We2 : We1;
        g_Weh[layer][n * 64 + k] = __float2half(We[j]);
    } else if (bx < PB_CONCAT + PB_PREP + PB_GATHER) {
        int idx = (bx - PB_CONCAT - PB_PREP) * 256 + tid;
        int i = idx >> 4;
        int c = (idx & 15) * 8;
        const float4* src = (const float4*)&emb[(size_t)n_id[i] * 128 + c];
        float4 v0 = src[0], v1 = src[1];
        uint4 o;
        o.x = h2u(__floats2half2_rn(v0.x, v0.y));
        o.y = h2u(__floats2half2_rn(v0.z, v0.w));
        o.z = h2u(__floats2half2_rn(v1.x, v1.y));
        o.w = h2u(__floats2half2_rn(v1.z, v1.w));
        *(uint4*)&g_xh[i * 128 + c] = o;
    } else {
        int e = (bx - PB_CONCAT - PB_PREP - PB_GATHER) * 256 + tid;
        if (e < NE && ei[NE + e] < BATCH) {
            int slot = atomicAdd(&g_cnt, 1);
            g_eidx[slot] = e;
        }
    }
}

// ---------------- shared GEMM tile body (fp16 m16n8k16, cp.async 2-stage) ---
__device__ __forceinline__ void gemm_tile_body(
    const __half* __restrict__ A, const __half* __restrict__ W,
    const float* __restrict__ bias, __half* __restrict__ Cq,
    __half* __restrict__ Cs, int M, int m0, int n0) {
    __shared__ __half As[2][128][40];
    __shared__ __half Bs[2][128][40];
    const int tid = threadIdx.x;
    const int lane = tid & 31, wid = tid >> 5;
    const int wm = (wid & 3) * 32, wn = (wid >> 2) * 64;
    const int g = lane >> 2, t = lane & 3;
    const int lrow = tid >> 1;
    const int lcol = (tid & 1) * 16;
    const int gr = m0 + lrow;
    const bool aval = gr < M;
    const __half* abase = &A[(size_t)(aval ? gr : 0) * 128 + lcol];
    const __half* bbase = &W[(size_t)(n0 + lrow) * 128 + lcol];

    float acc[2][8][4];
#pragma unroll
    for (int i = 0; i < 2; i++)
#pragma unroll
        for (int j = 0; j < 8; j++)
#pragma unroll
            for (int c = 0; c < 4; c++) acc[i][j][c] = 0.f;

#pragma unroll
    for (int it = 0; it < 2; it++) {
        int k0 = it * 32;
        cp16(&As[it][lrow][lcol],     abase + k0, aval);
        cp16(&As[it][lrow][lcol + 8], abase + k0 + 8, aval);
        cp16(&Bs[it][lrow][lcol],     bbase + k0, true);
        cp16(&Bs[it][lrow][lcol + 8], bbase + k0 + 8, true);
        asm volatile("cp.async.commit_group;" ::: "memory");
    }

#pragma unroll
    for (int it = 0; it < 4; it++) {
        if (it < 3)
            asm volatile("cp.async.wait_group 1;" ::: "memory");
        else
            asm volatile("cp.async.wait_group 0;" ::: "memory");
        __syncthreads();
        const int buf = it & 1;
#pragma unroll
        for (int kk = 0; kk < 32; kk += 16) {
            unsigned af[2][4];
#pragma unroll
            for (int i = 0; i < 2; i++) {
                int r = wm + i * 16 + g;
                af[i][0] = *(const unsigned*)&As[buf][r][kk + 2 * t];
                af[i][1] = *(const unsigned*)&As[buf][r + 8][kk + 2 * t];
                af[i][2] = *(const unsigned*)&As[buf][r][kk + 2 * t + 8];
                af[i][3] = *(const unsigned*)&As[buf][r + 8][kk + 2 * t + 8];
            }
            unsigned bf[8][2];
#pragma unroll
            for (int j = 0; j < 8; j++) {
                int n = wn + j * 8 + g;
                bf[j][0] = *(const unsigned*)&Bs[buf][n][kk + 2 * t];
                bf[j][1] = *(const unsigned*)&Bs[buf][n][kk + 2 * t + 8];
            }
#pragma unroll
            for (int i = 0; i < 2; i++)
#pragma unroll
                for (int j = 0; j < 8; j++) {
                    float* c = acc[i][j];
                    asm volatile(
                        "mma.sync.aligned.m16n8k16.row.col.f32.f16.f16.f32 "
                        "{%0,%1,%2,%3}, {%4,%5,%6,%7}, {%8,%9}, {%0,%1,%2,%3};"
                        : "+f"(c[0]), "+f"(c[1]), "+f"(c[2]), "+f"(c[3])
                        : "r"(af[i][0]), "r"(af[i][1]), "r"(af[i][2]),
                          "r"(af[i][3]), "r"(bf[j][0]), "r"(bf[j][1]));
                }
        }
        __syncthreads();
        if (it + 2 < 4) {
            int k0 = (it + 2) * 32;
            cp16(&As[buf][lrow][lcol],     abase + k0, aval);
            cp16(&As[buf][lrow][lcol + 8], abase + k0 + 8, aval);
            cp16(&Bs[buf][lrow][lcol],     bbase + k0, true);
            cp16(&Bs[buf][lrow][lcol + 8], bbase + k0 + 8, true);
            asm volatile("cp.async.commit_group;" ::: "memory");
        }
    }
#pragma unroll
    for (int i = 0; i < 2; i++) {
        int r0 = m0 + wm + i * 16 + g;
#pragma unroll
        for (int j = 0; j < 8; j++) {
            int col = n0 + wn + j * 8 + t * 2;
            float b0 = bias[col], b1 = bias[col + 1];
#pragma unroll
            for (int rr = 0; rr < 2; rr++) {
                int row = r0 + rr * 8;
                if (row < M) {
                    float o0 = acc[i][j][rr * 2 + 0] + b0;
                    float o1 = acc[i][j][rr * 2 + 1] + b1;
                    if (col < 384) {
                        *(__half2*)&Cq[(size_t)row * 384 + col] =
                            __floats2half2_rn(o0, o1);
                    } else {
                        *(__half2*)&Cs[(size_t)row * 128 + col - 384] =
                            __floats2half2_rn(o0, o1);
                    }
                }
            }
        }
    }
}

// layer-1 node GEMM: grid (391, 4)
__global__ __launch_bounds__(256) void node_gemm_h(
    const __half* __restrict__ A, const __half* __restrict__ W,
    const float* __restrict__ bias, __half* __restrict__ Cq,
    __half* __restrict__ Cs) {
    gemm_tile_body(A, W, bias, Cq, Cs, NN, blockIdx.x * 128, blockIdx.y * 128);
}

// layer-2 node GEMM, single launch: q(BATCH) | k,v(NN) | s(BATCH)
__global__ __launch_bounds__(256) void node_gemm_l2(
    const __half* __restrict__ A, const __half* __restrict__ W,
    const float* __restrict__ bias, __half* __restrict__ Cq,
    __half* __restrict__ Cs) {
    const int GB_B = (BATCH + 127) / 128;   // 79
    const int GB_N = (NN + 127) / 128;      // 391
    int bx = blockIdx.x;
    int m0, n0, M;
    if (bx < GB_B) {
        m0 = bx * 128; n0 = 0; M = BATCH;
    } else if (bx < GB_B + 2 * GB_N) {
        int idx = bx - GB_B;
        m0 = (idx % GB_N) * 128; n0 = 128 + (idx / GB_N) * 128; M = NN;
    } else {
        m0 = (bx - GB_B - 2 * GB_N) * 128; n0 = 384; M = BATCH;
    }
    gemm_tile_body(A, W, bias, Cq, Cs, M, m0, n0);
}

// ===== FUSED edge kernel: attr build + E GEMM (smem) + alpha/agg atomics =====
__global__ __launch_bounds__(256) void edge_fused(
    const float* __restrict__ feats, const float* __restrict__ times,
    const float* __restrict__ tw, const float* __restrict__ tb,
    const __half* __restrict__ Weh,
    const int* __restrict__ eidx, const int* __restrict__ cntp, int cnt_c,
    const int* __restrict__ ei, const __half* __restrict__ qkv,
    float* __restrict__ s, float* __restrict__ acc) {
    const int cnt = cntp ? *cntp : cnt_c;
    const int m0 = blockIdx.x * 128;
    if (m0 >= cnt) return;

    __shared__ __align__(16) char sbuf[36864];
    __half (*As)[72] = (__half(*)[72])sbuf;                 // [128][72]
    __half (*Bs)[72] = (__half(*)[72])(sbuf + 18432);       // [128][72]
    __half (*Es)[136] = (__half(*)[136])sbuf;               // overlaps (phase 2+)

    const int tid = threadIdx.x;
    const int lane = tid & 31, wid = tid >> 5;
    const int wm = (wid & 3) * 32, wn = (wid >> 2) * 64;
    const int g = lane >> 2, t = lane & 3;

    float accf[2][8][4];
#pragma unroll
    for (int i = 0; i < 2; i++)
#pragma unroll
        for (int j = 0; j < 8; j++)
#pragma unroll
            for (int c = 0; c < 4; c++) accf[i][j][c] = 0.f;

    // ---- phase 1: build A (edge attr) + B (We) tiles ----
    const int lrow = tid >> 1;
    const int hs = tid & 1;
    {
        int r = m0 + lrow;
        bool valid = r < cnt;
        int eid = valid ? (eidx ? eidx[r] : r) : 0;
        if (hs == 0) {   // feats cols 0..31
#pragma unroll
            for (int c = 0; c < 4; c++) {
                float4 v0, v1;
                if (valid) {
                    const float4* fp = (const float4*)&feats[(size_t)eid * 32 + c * 8];
                    v0 = fp[0]; v1 = fp[1];
                } else {
                    v0 = v1 = make_float4(0.f, 0.f, 0.f, 0.f);
                }
                uint4 o;
                o.x = h2u(__floats2half2_rn(v0.x, v0.y));
                o.y = h2u(__floats2half2_rn(v0.z, v0.w));
                o.z = h2u(__floats2half2_rn(v1.x, v1.y));
                o.w = h2u(__floats2half2_rn(v1.z, v1.w));
                *(uint4*)&As[lrow][c * 8] = o;
            }
        } else {         // time-embedding cols 32..63
            float tv = valid ? times[eid] : 0.f;
#pragma unroll
            for (int c = 0; c < 4; c++) {
                float cv[8];
#pragma unroll
                for (int u = 0; u < 8; u++) {
                    int j = c * 8 + u;
                    cv[u] = __cosf(tv * __ldg(&tw[j]) + __ldg(&tb[j]));
                }
                uint4 o;
                o.x = h2u(__floats2half2_rn(cv[0], cv[1]));
                o.y = h2u(__floats2half2_rn(cv[2], cv[3]));
                o.z = h2u(__floats2half2_rn(cv[4], cv[5]));
                o.w = h2u(__floats2half2_rn(cv[6], cv[7]));
                *(uint4*)&As[lrow][32 + c * 8] = o;
            }
        }
        const uint4* bp = (const uint4*)&Weh[lrow * 64 + hs * 32];
        uint4* bd = (uint4*)&Bs[lrow][hs * 32];
        bd[0] = bp[0]; bd[1] = bp[1]; bd[2] = bp[2]; bd[3] = bp[3];
    }

    // ---- prefetch src/dst for this warp's 16 edges (coalesced, pre-sync) ----
    const int base = wid * 16;
    int pf_sd;
    {
        int u = lane & 15;
        int r = m0 + base + u;
        int rr = r < cnt ? r : cnt - 1;
        int eid = eidx ? __ldg(&eidx[rr]) : rr;
        pf_sd = (lane < 16) ? __ldg(&ei[eid]) : __ldg(&ei[NE + eid]);
    }
    __syncthreads();

    // ---- MMA over K=64 ----
#pragma unroll
    for (int kk = 0; kk < 64; kk += 16) {
        unsigned af[2][4];
#pragma unroll
        for (int i = 0; i < 2; i++) {
            int r = wm + i * 16 + g;
            af[i][0] = *(const unsigned*)&As[r][kk + 2 * t];
            af[i][1] = *(const unsigned*)&As[r + 8][kk + 2 * t];
            af[i][2] = *(const unsigned*)&As[r][kk + 2 * t + 8];
            af[i][3] = *(const unsigned*)&As[r + 8][kk + 2 * t + 8];
        }
        unsigned bf[8][2];
#pragma unroll
        for (int j = 0; j < 8; j++) {
            int n = wn + j * 8 + g;
            bf[j][0] = *(const unsigned*)&Bs[n][kk + 2 * t];
            bf[j][1] = *(const unsigned*)&Bs[n][kk + 2 * t + 8];
        }
#pragma unroll
        for (int i = 0; i < 2; i++)
#pragma unroll
            for (int j = 0; j < 8; j++) {
                float* c = accf[i][j];
                asm volatile(
                    "mma.sync.aligned.m16n8k16.row.col.f32.f16.f16.f32 "
                    "{%0,%1,%2,%3}, {%4,%5,%6,%7}, {%8,%9}, {%0,%1,%2,%3};"
                    : "+f"(c[0]), "+f"(c[1]), "+f"(c[2]), "+f"(c[3])
                    : "r"(af[i][0]), "r"(af[i][1]), "r"(af[i][2]),
                      "r"(af[i][3]), "r"(bf[j][0]), "r"(bf[j][1]));
            }
    }
    __syncthreads();   // done reading As/Bs — safe to overwrite with Es

    // ---- phase 2: stage E tile into smem ----
#pragma unroll
    for (int i = 0; i < 2; i++) {
        int r0 = wm + i * 16 + g;
#pragma unroll
        for (int j = 0; j < 8; j++) {
            int col = wn + j * 8 + t * 2;
#pragma unroll
            for (int rr = 0; rr < 2; rr++)
                *(__half2*)&Es[r0 + rr * 8][col] = __floats2half2_rn(
                    accf[i][j][rr * 2 + 0], accf[i][j][rr * 2 + 1]);
        }
    }
    __syncthreads();

    // ---- phase 3: per-edge alpha + aggregation, depth-2 software pipeline ---
    // nvalid is warp-uniform
    int nvalid = cnt - (m0 + base);
    nvalid = nvalid < 0 ? 0 : (nvalid > 16 ? 16 : nvalid);
    if (nvalid > 0) {
        int dst_c;
        uint2 eraw, qraw, kraw, vraw;
        {
            int src0 = __shfl_sync(0xffffffffu, pf_sd, 0);
            dst_c = __shfl_sync(0xffffffffu, pf_sd, 16);
            eraw = *(const uint2*)&Es[base][lane * 4];
            qraw = *(const uint2*)&qkv[(size_t)dst_c * 384 + lane * 4];
            kraw = *(const uint2*)&qkv[(size_t)src0 * 384 + 128 + lane * 4];
            vraw = *(const uint2*)&qkv[(size_t)src0 * 384 + 256 + lane * 4];
        }
#pragma unroll 4
        for (int u = 0; u < 16; u++) {
            if (u >= nvalid) break;
            uint2 ec = eraw, qc = qraw, kc = kraw, vc = vraw;
            int dstc = dst_c;
            if (u + 1 < 16) {
                int un = (u + 1 < nvalid) ? u + 1 : nvalid - 1;
                int srcn = __shfl_sync(0xffffffffu, pf_sd, un);
                dst_c = __shfl_sync(0xffffffffu, pf_sd, un + 16);
                eraw = *(const uint2*)&Es[base + un][lane * 4];
                qraw = *(const uint2*)&qkv[(size_t)dst_c * 384 + lane * 4];
                kraw = *(const uint2*)&qkv[(size_t)srcn * 384 + 128 + lane * 4];
                vraw = *(const uint2*)&qkv[(size_t)srcn * 384 + 256 + lane * 4];
            }
            float2 e01 = __half22float2(*reinterpret_cast<__half2*>(&ec.x));
            float2 e23 = __half22float2(*reinterpret_cast<__half2*>(&ec.y));
            float2 q01 = __half22float2(*reinterpret_cast<__half2*>(&qc.x));
            float2 q23 = __half22float2(*reinterpret_cast<__half2*>(&qc.y));
            float2 k01 = __half22float2(*reinterpret_cast<__half2*>(&kc.x));
            float2 k23 = __half22float2(*reinterpret_cast<__half2*>(&kc.y));
            float2 v01 = __half22float2(*reinterpret_cast<__half2*>(&vc.x));
            float2 v23 = __half22float2(*reinterpret_cast<__half2*>(&vc.y));
            float p = q01.x * (k01.x + e01.x) + q01.y * (k01.y + e01.y) +
                      q23.x * (k23.x + e23.x) + q23.y * (k23.y + e23.y);
            p += __shfl_xor_sync(0xffffffffu, p, 1, 8);
            p += __shfl_xor_sync(0xffffffffu, p, 2, 8);
            p += __shfl_xor_sync(0xffffffffu, p, 4, 8);
            float a = __expf(p * 0.17677669529663687f);   // 1/sqrt(32)
            float ah1 = __shfl_sync(0xffffffffu, a, 8);
            float ah2 = __shfl_sync(0xffffffffu, a, 16);
            float ah3 = __shfl_sync(0xffffffffu, a, 24);
            if (lane == 0) {
                float* sp = &s[dstc * 4];
                asm volatile("red.global.add.v4.f32 [%0], {%1,%2,%3,%4};"
                             :: "l"(sp), "f"(a), "f"(ah1), "f"(ah2), "f"(ah3));
            }
            float4 m = make_float4(a * (v01.x + e01.x), a * (v01.y + e01.y),
                                   a * (v23.x + e23.x), a * (v23.y + e23.y));
            float* op = &acc[(size_t)dstc * 128 + lane * 4];
            asm volatile("red.global.add.v4.f32 [%0], {%1,%2,%3,%4};"
                         :: "l"(op), "f"(m.x), "f"(m.y), "f"(m.z), "f"(m.w));
        }
    }
}

// ------- layer-1 normalize: out = relu(skip + acc/s) -> fp16 -------
__global__ void norm_kernel(const __half* __restrict__ skip,
                            const float* __restrict__ acc,
                            const float* __restrict__ s,
                            __half* __restrict__ outp) {
    int idx = blockIdx.x * blockDim.x + threadIdx.x;
    if (idx >= NN * 32) return;
    int n = idx >> 5, c4 = idx & 31;
    float inv = 1.f / (s[n * 4 + (c4 >> 3)] + 1e-16f);
    float4 a = *(const float4*)&acc[n * 128 + c4 * 4];
    uint2 sk = *(const uint2*)&skip[(size_t)n * 128 + c4 * 4];
    float2 s01 = __half22float2(*reinterpret_cast<__half2*>(&sk.x));
    float2 s23 = __half22float2(*reinterpret_cast<__half2*>(&sk.y));
    float4 o = make_float4(fmaxf(s01.x + a.x * inv, 0.f),
                           fmaxf(s01.y + a.y * inv, 0.f),
                           fmaxf(s23.x + a.z * inv, 0.f),
                           fmaxf(s23.y + a.w * inv, 0.f));
    uint2 h;
    h.x = h2u(__floats2half2_rn(o.x, o.y));
    h.y = h2u(__floats2half2_rn(o.z, o.w));
    *(uint2*)&outp[(size_t)n * 128 + c4 * 4] = h;
}

// ------- layer-2 normalize + projection fused: y = (skip + acc/s) @ pW + pb --
__global__ __launch_bounds__(256) void norm_proj_kernel(
    const __half* __restrict__ skip, const float* __restrict__ acc,
    const float* __restrict__ s, const float* __restrict__ pW,
    const float* __restrict__ pb, float* __restrict__ y) {
    __shared__ float xrow[8][128];
    int wid = threadIdx.x >> 5, lane = threadIdx.x & 31;
    int row = blockIdx.x * 8 + wid;
    if (row >= BATCH) return;
    float inv = 1.f / (s[row * 4 + (lane >> 3)] + 1e-16f);
    float4 a = *(const float4*)&acc[(size_t)row * 128 + lane * 4];
    uint2 sk = *(const uint2*)&skip[(size_t)row * 128 + lane * 4];
    float2 s01 = __half22float2(*reinterpret_cast<__half2*>(&sk.x));
    float2 s23 = __half22float2(*reinterpret_cast<__half2*>(&sk.y));
    xrow[wid][lane * 4 + 0] = s01.x + a.x * inv;
    xrow[wid][lane * 4 + 1] = s01.y + a.y * inv;
    xrow[wid][lane * 4 + 2] = s23.x + a.z * inv;
    xrow[wid][lane * 4 + 3] = s23.y + a.w * inv;
    __syncwarp();
    float accv = pb[lane];
#pragma unroll 8
    for (int k = 0; k < 128; k++)
        accv += xrow[wid][k] * pW[k * 32 + lane];
    y[row * 32 + lane] = accv;
}

// ---------------- host launch ----------------
extern "C" void kernel_launch(void* const* d_in, const int* in_sizes, int n_in,
                              void* d_out, int out_size) {
    int off = (n_in >= 28) ? 1 : 0;
    const int* n_id       = (const int*)d_in[0];
    const int* ei         = (const int*)d_in[1];
    const float* times    = (const float*)d_in[2];
    const float* feats    = (const float*)d_in[3];
    const float* node_emb = (const float*)d_in[4 + off];
    const float* tw       = (const float*)d_in[5 + off];
    const float* tb       = (const float*)d_in[6 + off];
    const float* q1W = (const float*)d_in[7 + off],  *q1b = (const float*)d_in[8 + off];
    const float* k1W = (const float*)d_in[9 + off],  *k1b = (const float*)d_in[10 + off];
    const float* v1W = (const float*)d_in[11 + off], *v1b = (const float*)d_in[12 + off];
    const float* e1W = (const float*)d_in[13 + off];
    const float* s1W = (const float*)d_in[14 + off], *s1b = (const float*)d_in[15 + off];
    const float* q2W = (const float*)d_in[16 + off], *q2b = (const float*)d_in[17 + off];
    const float* k2W = (const float*)d_in[18 + off], *k2b = (const float*)d_in[19 + off];
    const float* v2W = (const float*)d_in[20 + off], *v2b = (const float*)d_in[21 + off];
    const float* e2W = (const float*)d_in[22 + off];
    const float* s2W = (const float*)d_in[23 + off], *s2b = (const float*)d_in[24 + off];
    const float* pW  = (const float*)d_in[25 + off], *pb  = (const float*)d_in[26 + off];

    float *p_accs, *p_bc0, *p_bc1;
    __half *p_xh, *p_qkv, *p_skip, *p_Wch0, *p_Wch1, *p_Weh0, *p_Weh1;
    int *p_eidx, *p_cnt;
    cudaGetSymbolAddress((void**)&p_xh, g_xh);
    cudaGetSymbolAddress((void**)&p_qkv, g_qkvh);
    cudaGetSymbolAddress((void**)&p_skip, g_skiph);
    cudaGetSymbolAddress((void**)&p_accs, g_accs);
    cudaGetSymbolAddress((void**)&p_Wch0, g_Wch);
    p_Wch1 = p_Wch0 + 512 * 128;
    cudaGetSymbolAddress((void**)&p_bc0, g_bc);
    p_bc1 = p_bc0 + 512;
    cudaGetSymbolAddress((void**)&p_Weh0, g_Weh);
    p_Weh1 = p_Weh0 + 128 * 64;
    cudaGetSymbolAddress((void**)&p_eidx, g_eidx);
    cudaGetSymbolAddress((void**)&p_cnt, g_cnt);

    float* p_acc = p_accs;                     // NN*128
    float* p_s   = p_accs + (size_t)NN * 128;  // NN*4

    const int GB_N = (NN + 127) / 128;      // 391
    const int GB_B = (BATCH + 127) / 128;   // 79
    const int GB_E = (NE + 127) / 128;      // 3907
    const int GB_E2 = 977;                  // covers cnt up to 125k edges
    const int PROLOGUE_BLKS = PB_CONCAT + PB_PREP + PB_GATHER + PB_COMPACT;

    // ----- prologue -----
    cudaMemsetAsync(p_cnt, 0, sizeof(int));
    prologue<<<PROLOGUE_BLKS, 256>>>(n_id, node_emb, ei,
                                     q1W, k1W, v1W, s1W, q1b, k1b, v1b, s1b,
                                     q2W, k2W, v2W, s2W, q2b, k2b, v2b, s2b,
                                     e1W, e2W);

    // ----- layer 1 (all nodes, all edges) -----
    node_gemm_h<<<dim3(GB_N, 4), 256>>>(p_xh, p_Wch0, p_bc0, p_qkv, p_skip);
    cudaMemsetAsync(p_accs, 0, (size_t)NN * 132 * sizeof(float));
    edge_fused<<<GB_E, 256>>>(feats, times, tw, tb, p_Weh0, nullptr, nullptr, NE,
                              ei, p_qkv, p_s, p_acc);
    norm_kernel<<<(NN * 32 + 255) / 256, 256>>>(p_skip, p_acc, p_s, p_xh);

    // ----- layer 2 (only dst < BATCH matters) -----
    node_gemm_l2<<<GB_B + 2 * GB_N + GB_B, 256>>>(p_xh, p_Wch1, p_bc1, p_qkv,
                                                  p_skip);
    cudaMemsetAsync(p_acc, 0, (size_t)BATCH * 128 * sizeof(float));
    cudaMemsetAsync(p_s, 0, BATCH * 4 * sizeof(float));
    edge_fused<<<GB_E2, 256>>>(feats, times, tw, tb, p_Weh1, p_eidx, p_cnt, 0,
                               ei, p_qkv, p_s, p_acc);
    norm_proj_kernel<<<(BATCH + 7) / 8, 256>>>(p_skip, p_acc, p_s, pW, pb,
                                               (float*)d_out);
}